// round 1
// baseline (speedup 1.0000x reference)
#include <cuda_runtime.h>
#include <math.h>
#include <stdint.h>

#define BB 32
#define TT_LEN 2048
#define DD 512
#define NH 1024        // complex FFT length (real length 2048)
#define KSEL 16
#define PI_D 3.14159265358979323846

// ---------------- device scratch (no allocations allowed) ----------------
__device__ float2 d_tw[NH / 2];      // FFT twiddles exp(-2pi i j / 1024)
__device__ float2 d_twu[NH];         // untangle twiddles exp(-2pi i k / 2048)
__device__ float  d_cwT[NH];         // cos(omega_k)
__device__ float  d_swT[NH];         // sin(omega_k)
__device__ float  d_omT[NH];         // omega_k = 2pi k / (2048*2047)
__device__ float  d_amp[BB * DD * KSEL];
__device__ float  d_phs[BB * DD * KSEL];
__device__ int    d_kix[BB * DD * KSEL];

// ---------------- init: twiddle + rotation tables (double precision) -----
__global__ void init_tables() {
    int i = threadIdx.x;  // 1024 threads, 1 block
    if (i < NH / 2) {
        double a = -2.0 * PI_D * (double)i / (double)NH;
        d_tw[i] = make_float2((float)cos(a), (float)sin(a));
    }
    if (i < NH) {
        double a = -2.0 * PI_D * (double)i / (double)(2 * NH);
        d_twu[i] = make_float2((float)cos(a), (float)sin(a));
        double om = 2.0 * PI_D * (double)i / ((double)TT_LEN * (double)(TT_LEN - 1));
        d_omT[i] = (float)om;
        d_cwT[i] = (float)cos(om);
        d_swT[i] = (float)sin(om);
    }
}

__device__ __forceinline__ float2 cmulf(float2 a, float2 b) {
    return make_float2(a.x * b.x - a.y * b.y, a.x * b.y + a.y * b.x);
}

// Compute real-FFT bin k (1..1023) from the packed complex spectrum Z.
__device__ __forceinline__ float2 untangle(const float2* Z, int k) {
    float2 A  = Z[k];
    float2 Bv = Z[(NH - k) & (NH - 1)];
    float2 Bc = make_float2(Bv.x, -Bv.y);
    float2 E  = make_float2(0.5f * (A.x + Bc.x), 0.5f * (A.y + Bc.y));
    float2 Od = make_float2(A.x - Bc.x, A.y - Bc.y);
    float2 O  = make_float2(0.5f * Od.y, -0.5f * Od.x);  // Od / (2i)
    float2 e  = d_twu[k];
    float2 eo = cmulf(e, O);
    return make_float2(E.x + eo.x, E.y + eo.y);
}

// ---------------- analysis: FFT + top-16 per (b,d) -----------------------
__global__ __launch_bounds__(512) void analyze(const float* __restrict__ x) {
    __shared__ float2 Z[NH];
    __shared__ float  mag[NH];
    __shared__ float  rv[16];
    __shared__ int    ri[16];
    __shared__ int    selList[KSEL];

    const int tid = threadIdx.x;
    const int bd  = blockIdx.x;
    const int b   = bd >> 9;
    const int d   = bd & 511;
    const float* xb = x + (size_t)b * TT_LEN * DD + d;

    // load 2048 reals as 1024 complex, bit-reversed placement
    {
        int n1 = tid, n2 = tid + 512;
        float a0 = xb[(size_t)(2 * n1)     * DD];
        float a1 = xb[(size_t)(2 * n1 + 1) * DD];
        float b0 = xb[(size_t)(2 * n2)     * DD];
        float b1 = xb[(size_t)(2 * n2 + 1) * DD];
        Z[__brev((unsigned)n1) >> 22] = make_float2(a0, a1);
        Z[__brev((unsigned)n2) >> 22] = make_float2(b0, b1);
    }
    __syncthreads();

    // radix-2 DIT, 10 stages, 512 butterflies/stage (1 per thread)
#pragma unroll
    for (int s = 0; s < 10; s++) {
        int half = 1 << s;
        int pos  = tid & (half - 1);
        int i1   = ((tid >> s) << (s + 1)) + pos;
        int i2   = i1 + half;
        float2 w  = d_tw[pos << (9 - s)];
        float2 a  = Z[i1];
        float2 t  = cmulf(w, Z[i2]);
        Z[i1] = make_float2(a.x + t.x, a.y + t.y);
        Z[i2] = make_float2(a.x - t.x, a.y - t.y);
        __syncthreads();
    }

    // |X_k|^2 for k = 1..1023 (bin 0 excluded via sentinel)
#pragma unroll
    for (int q = 0; q < 2; q++) {
        int k = tid + q * 512;
        float m = -1e30f;
        if (k != 0) {
            float2 Xk = untangle(Z, k);
            m = Xk.x * Xk.x + Xk.y * Xk.y;
        }
        mag[k] = m;
    }
    __syncthreads();

    // top-16 via 16 rounds of two-level shuffle argmax
    const int lane = tid & 31;
    const int warp = tid >> 5;
    for (int r = 0; r < KSEL; r++) {
        float v1 = mag[tid], v2 = mag[tid + 512];
        float v; int id;
        if (v2 > v1) { v = v2; id = tid + 512; } else { v = v1; id = tid; }
#pragma unroll
        for (int o = 16; o > 0; o >>= 1) {
            float ov = __shfl_down_sync(0xffffffffu, v, o);
            int   oi = __shfl_down_sync(0xffffffffu, id, o);
            if (ov > v) { v = ov; id = oi; }
        }
        if (lane == 0) { rv[warp] = v; ri[warp] = id; }
        __syncthreads();
        if (warp == 0) {
            v  = (lane < 16) ? rv[lane] : -2e30f;
            id = (lane < 16) ? ri[lane] : 0;
#pragma unroll
            for (int o = 8; o > 0; o >>= 1) {
                float ov = __shfl_down_sync(0xffffffffu, v, o);
                int   oi = __shfl_down_sync(0xffffffffu, id, o);
                if (ov > v) { v = ov; id = oi; }
            }
            if (lane == 0) { selList[r] = id; mag[id] = -1e30f; }
        }
        __syncthreads();
    }

    // emit amp/phase/bin for the 16 selected bins
    if (tid < KSEL) {
        int k = selList[tid];
        float2 Xk = untangle(Z, k);
        float amp = sqrtf(Xk.x * Xk.x + Xk.y * Xk.y);
        float ph  = atan2f(Xk.y, Xk.x);
        int base = bd * KSEL + tid;
        d_amp[base] = amp;
        d_phs[base] = ph;
        d_kix[base] = k;
    }
}

// ---------------- synthesis: rotation recurrence --------------------------
#define TTILE 256
__global__ __launch_bounds__(256) void synth(float* __restrict__ out) {
    __shared__ float s_cw[NH], s_sw[NH], s_om[NH];
    for (int i = threadIdx.x; i < NH; i += 256) {
        s_cw[i] = d_cwT[i];
        s_sw[i] = d_swT[i];
        s_om[i] = d_omT[i];
    }
    __syncthreads();

    const int b  = blockIdx.z;
    const int d  = blockIdx.y * 256 + threadIdx.x;
    const int t0 = blockIdx.x * TTILE;
    const int base = (b * DD + d) * KSEL;

    float c[KSEL], s[KSEL], cw[KSEL], sw[KSEL];
#pragma unroll
    for (int r = 0; r < KSEL; r++) {
        int   k   = d_kix[base + r];
        float amp = d_amp[base + r];
        float ph  = d_phs[base + r];
        float om  = s_om[k];
        cw[r] = s_cw[k];
        sw[r] = s_sw[k];
        float ang = fmaf(om, (float)t0, ph);
        float sv, cv;
        sincosf(ang, &sv, &cv);
        c[r] = amp * cv;
        s[r] = amp * sv;
    }

    float* po = out + ((size_t)b * TT_LEN + t0) * DD + d;
#pragma unroll 4
    for (int tt = 0; tt < TTILE; tt++) {
        float acc = 0.f;
#pragma unroll
        for (int r = 0; r < KSEL; r++) acc += c[r];
        po[(size_t)tt * DD] = acc;
#pragma unroll
        for (int r = 0; r < KSEL; r++) {
            float nc = fmaf(c[r], cw[r], -s[r] * sw[r]);
            float ns = fmaf(s[r], cw[r],  c[r] * sw[r]);
            c[r] = nc;
            s[r] = ns;
        }
    }
}

// ---------------- launch ---------------------------------------------------
extern "C" void kernel_launch(void* const* d_in, const int* in_sizes, int n_in,
                              void* d_out, int out_size) {
    const float* x = (const float*)d_in[0];
    float* out = (float*)d_out;

    init_tables<<<1, 1024>>>();
    analyze<<<BB * DD, 512>>>(x);
    synth<<<dim3(TT_LEN / TTILE, DD / 256, BB), 256>>>(out);
}

// round 2
// speedup vs baseline: 1.1835x; 1.1835x over previous
#include <cuda_runtime.h>
#include <math.h>
#include <stdint.h>

#define BB 32
#define TT_LEN 2048
#define DD 512
#define NH 1024        // complex FFT length (real length 2048)
#define KSEL 16
#define TTILE 128
#define NM (TT_LEN / TTILE)   // 16 tile-seeding rotations
#define PI_D 3.14159265358979323846

// ---------------- device scratch (no allocations allowed) ----------------
__device__ float  d_xt[(size_t)BB * DD * TT_LEN];   // transposed input [b][d][t]
__device__ float2 d_tw[NH / 2];      // FFT twiddles exp(-2pi i j / 1024)
__device__ float2 d_twu[NH];         // untangle twiddles exp(-2pi i k / 2048)
__device__ float  d_cwT[NH];         // cos(omega_k)
__device__ float  d_swT[NH];         // sin(omega_k)
__device__ float2 d_rot0[NM * NH];   // e^{i omega_k * TTILE * m}
__device__ float  d_c0[BB * DD * KSEL];   // amp*cos(ph)  (= Re Xk)
__device__ float  d_s0[BB * DD * KSEL];   // amp*sin(ph)  (= Im Xk)
__device__ int    d_kix[BB * DD * KSEL];

// ---------------- packed f32x2 helpers ------------------------------------
typedef unsigned long long u64;
__device__ __forceinline__ u64 pk(float lo, float hi) {
    u64 r; asm("mov.b64 %0,{%1,%2};" : "=l"(r) : "f"(lo), "f"(hi)); return r;
}
__device__ __forceinline__ void upk(u64 v, float& lo, float& hi) {
    asm("mov.b64 {%0,%1},%2;" : "=f"(lo), "=f"(hi) : "l"(v));
}
#define F2MUL(d,a,b)   asm("mul.rn.f32x2 %0,%1,%2;"    : "=l"(d) : "l"(a), "l"(b))
#define F2ADD(d,a,b)   asm("add.rn.f32x2 %0,%1,%2;"    : "=l"(d) : "l"(a), "l"(b))
#define F2FMA(d,a,b,c) asm("fma.rn.f32x2 %0,%1,%2,%3;" : "=l"(d) : "l"(a), "l"(b), "l"(c))

// ---------------- init: all tables (double precision) ---------------------
__global__ void init_tables() {
    int gid = blockIdx.x * blockDim.x + threadIdx.x;   // 64*256 = 16384
    if (gid < NH / 2) {
        double a = -2.0 * PI_D * (double)gid / (double)NH;
        d_tw[gid] = make_float2((float)cos(a), (float)sin(a));
    }
    if (gid < NH) {
        double a = -2.0 * PI_D * (double)gid / (double)(2 * NH);
        d_twu[gid] = make_float2((float)cos(a), (float)sin(a));
        double om = 2.0 * PI_D * (double)gid / ((double)TT_LEN * (double)(TT_LEN - 1));
        d_cwT[gid] = (float)cos(om);
        d_swT[gid] = (float)sin(om);
    }
    if (gid < NM * NH) {
        int m = gid >> 10, k = gid & (NH - 1);
        double om = 2.0 * PI_D * (double)k / ((double)TT_LEN * (double)(TT_LEN - 1));
        double a = om * (double)(TTILE * m);
        d_rot0[gid] = make_float2((float)cos(a), (float)sin(a));
    }
}

// ---------------- transpose: x[b][t][d] -> d_xt[b][d][t] -------------------
__global__ __launch_bounds__(256) void transpose(const float* __restrict__ x) {
    __shared__ float tile[32][33];
    const int b  = blockIdx.z;
    const int t0 = blockIdx.x * 32;
    const int d0 = blockIdx.y * 32;
    const int lx = threadIdx.x;   // 0..31
    const int ly = threadIdx.y;   // 0..7
#pragma unroll
    for (int i = 0; i < 32; i += 8)
        tile[ly + i][lx] = x[((size_t)b * TT_LEN + t0 + ly + i) * DD + d0 + lx];
    __syncthreads();
#pragma unroll
    for (int i = 0; i < 32; i += 8)
        d_xt[((size_t)b * DD + d0 + ly + i) * TT_LEN + t0 + lx] = tile[lx][ly + i];
}

__device__ __forceinline__ float2 cmulf(float2 a, float2 b) {
    return make_float2(a.x * b.x - a.y * b.y, a.x * b.y + a.y * b.x);
}

// Real-FFT bin k (1..1023) from packed complex spectrum Z.
__device__ __forceinline__ float2 untangle(const float2* Z, int k) {
    float2 A  = Z[k];
    float2 Bv = Z[(NH - k) & (NH - 1)];
    float2 Bc = make_float2(Bv.x, -Bv.y);
    float2 E  = make_float2(0.5f * (A.x + Bc.x), 0.5f * (A.y + Bc.y));
    float2 Od = make_float2(A.x - Bc.x, A.y - Bc.y);
    float2 O  = make_float2(0.5f * Od.y, -0.5f * Od.x);
    float2 e  = d_twu[k];
    float2 eo = cmulf(e, O);
    return make_float2(E.x + eo.x, E.y + eo.y);
}

// ---------------- analysis: FFT + top-16 per (b,d) -----------------------
__global__ __launch_bounds__(512) void analyze() {
    __shared__ float2 Z[NH];
    __shared__ float  mag[NH];
    __shared__ float  rv[16];
    __shared__ int    ri[16];
    __shared__ int    selList[KSEL];

    const int tid = threadIdx.x;
    const int bd  = blockIdx.x;
    const float2* row = (const float2*)(d_xt + (size_t)bd * TT_LEN);

    // coalesced load: 1024 complex points, bit-reversed placement
    {
        int n1 = tid, n2 = tid + 512;
        float2 v1 = row[n1];
        float2 v2 = row[n2];
        Z[__brev((unsigned)n1) >> 22] = v1;
        Z[__brev((unsigned)n2) >> 22] = v2;
    }
    __syncthreads();

#pragma unroll
    for (int s = 0; s < 10; s++) {
        int half = 1 << s;
        int pos  = tid & (half - 1);
        int i1   = ((tid >> s) << (s + 1)) + pos;
        int i2   = i1 + half;
        float2 w  = d_tw[pos << (9 - s)];
        float2 a  = Z[i1];
        float2 t  = cmulf(w, Z[i2]);
        Z[i1] = make_float2(a.x + t.x, a.y + t.y);
        Z[i2] = make_float2(a.x - t.x, a.y - t.y);
        __syncthreads();
    }

#pragma unroll
    for (int q = 0; q < 2; q++) {
        int k = tid + q * 512;
        float m = -1e30f;
        if (k != 0) {
            float2 Xk = untangle(Z, k);
            m = Xk.x * Xk.x + Xk.y * Xk.y;
        }
        mag[k] = m;
    }
    __syncthreads();

    const int lane = tid & 31;
    const int warp = tid >> 5;
    for (int r = 0; r < KSEL; r++) {
        float v1 = mag[tid], v2 = mag[tid + 512];
        float v; int id;
        if (v2 > v1) { v = v2; id = tid + 512; } else { v = v1; id = tid; }
#pragma unroll
        for (int o = 16; o > 0; o >>= 1) {
            float ov = __shfl_down_sync(0xffffffffu, v, o);
            int   oi = __shfl_down_sync(0xffffffffu, id, o);
            if (ov > v) { v = ov; id = oi; }
        }
        if (lane == 0) { rv[warp] = v; ri[warp] = id; }
        __syncthreads();
        if (warp == 0) {
            v  = (lane < 16) ? rv[lane] : -2e30f;
            id = (lane < 16) ? ri[lane] : 0;
#pragma unroll
            for (int o = 8; o > 0; o >>= 1) {
                float ov = __shfl_down_sync(0xffffffffu, v, o);
                int   oi = __shfl_down_sync(0xffffffffu, id, o);
                if (ov > v) { v = ov; id = oi; }
            }
            if (lane == 0) { selList[r] = id; mag[id] = -1e30f; }
        }
        __syncthreads();
    }

    if (tid < KSEL) {
        int k = selList[tid];
        float2 Xk = untangle(Z, k);            // Xk = amp * e^{i ph}
        int base = bd * KSEL + tid;
        d_c0[base]  = Xk.x;
        d_s0[base]  = Xk.y;
        d_kix[base] = k;
    }
}

// ---------------- synthesis: packed-f32x2 rotation recurrence -------------
__global__ __launch_bounds__(128) void synth(float* __restrict__ out) {
    __shared__ float s_cw[NH], s_sw[NH];
    for (int i = threadIdx.x; i < NH; i += 128) {
        s_cw[i] = d_cwT[i];
        s_sw[i] = d_swT[i];
    }
    __syncthreads();

    const int b  = blockIdx.z;
    const int d  = blockIdx.y * 128 + threadIdx.x;
    const int m  = blockIdx.x;          // tile index, t0 = m * TTILE
    const int base = (b * DD + d) * KSEL;
    const float2* rot = d_rot0 + m * NH;

    float cs[KSEL], ss[KSEL], cws[KSEL], sws[KSEL];
#pragma unroll
    for (int r = 0; r < KSEL; r++) {
        int    k  = d_kix[base + r];
        float  c0 = d_c0[base + r];
        float  s0 = d_s0[base + r];
        float2 rk = rot[k];
        cs[r]  = fmaf(c0, rk.x, -s0 * rk.y);   // rotate seed to t0 (exact table)
        ss[r]  = fmaf(c0, rk.y,  s0 * rk.x);
        cws[r] = s_cw[k];
        sws[r] = s_sw[k];
    }

    u64 C[8], S[8], CW[8], SW[8], NSW[8];
#pragma unroll
    for (int p = 0; p < 8; p++) {
        C[p]   = pk(cs[2 * p], cs[2 * p + 1]);
        S[p]   = pk(ss[2 * p], ss[2 * p + 1]);
        CW[p]  = pk(cws[2 * p], cws[2 * p + 1]);
        SW[p]  = pk(sws[2 * p], sws[2 * p + 1]);
        NSW[p] = pk(-sws[2 * p], -sws[2 * p + 1]);
    }

    float* po = out + ((size_t)b * TT_LEN + m * TTILE) * DD + d;
#pragma unroll 4
    for (int tt = 0; tt < TTILE; tt++) {
        // packed tree-sum of the 8 pair-accumulators
        u64 a0, a1, a2, a3;
        F2ADD(a0, C[0], C[1]);
        F2ADD(a1, C[2], C[3]);
        F2ADD(a2, C[4], C[5]);
        F2ADD(a3, C[6], C[7]);
        F2ADD(a0, a0, a1);
        F2ADD(a2, a2, a3);
        F2ADD(a0, a0, a2);
        float lo, hi;
        upk(a0, lo, hi);
        po[(size_t)tt * DD] = lo + hi;

        // packed rotation: c' = c*cw - s*sw ; s' = s*cw + c*sw
#pragma unroll
        for (int p = 0; p < 8; p++) {
            u64 t1, t2, nc, ns;
            F2MUL(t1, C[p], CW[p]);
            F2FMA(nc, S[p], NSW[p], t1);
            F2MUL(t2, S[p], CW[p]);
            F2FMA(ns, C[p], SW[p], t2);
            C[p] = nc;
            S[p] = ns;
        }
    }
}

// ---------------- launch ---------------------------------------------------
extern "C" void kernel_launch(void* const* d_in, const int* in_sizes, int n_in,
                              void* d_out, int out_size) {
    const float* x = (const float*)d_in[0];
    float* out = (float*)d_out;

    init_tables<<<64, 256>>>();
    transpose<<<dim3(TT_LEN / 32, DD / 32, BB), dim3(32, 8)>>>(x);
    analyze<<<BB * DD, 512>>>();
    synth<<<dim3(NM, DD / 128, BB), 128>>>(out);
}

// round 3
// speedup vs baseline: 2.1389x; 1.8073x over previous
#include <cuda_runtime.h>
#include <math.h>
#include <stdint.h>

#define BB 32
#define TT_LEN 2048
#define DD 512
#define NH 1024        // complex FFT length (real length 2048)
#define KSEL 16
#define TTILE 128
#define NM (TT_LEN / TTILE)
#define PI_D 3.14159265358979323846

// padded smem indexing: kills store bank conflicts in Stockham passes
#define IDX(i) ((i) + ((i) >> 5))
#define PADN (NH + NH / 32)   // 1056

// ---------------- device scratch ------------------------------------------
__device__ float  d_xt[(size_t)BB * DD * TT_LEN];   // transposed input [b][d][t]
__device__ float2 d_twf[256];        // exp(-2pi i j / 1024), j<256 (radix-4 twiddles)
__device__ float2 d_twu[NH];         // untangle twiddles exp(-2pi i k / 2048)
__device__ float  d_cwT[NH];         // cos(omega_k)
__device__ float  d_swT[NH];         // sin(omega_k)
__device__ float2 d_rot0[NM * NH];   // e^{i omega_k * TTILE * m}
__device__ float  d_c0[BB * DD * KSEL];
__device__ float  d_s0[BB * DD * KSEL];
__device__ int    d_kix[BB * DD * KSEL];

// ---------------- packed f32x2 helpers ------------------------------------
typedef unsigned long long u64;
__device__ __forceinline__ u64 pk(float lo, float hi) {
    u64 r; asm("mov.b64 %0,{%1,%2};" : "=l"(r) : "f"(lo), "f"(hi)); return r;
}
__device__ __forceinline__ void upk(u64 v, float& lo, float& hi) {
    asm("mov.b64 {%0,%1},%2;" : "=f"(lo), "=f"(hi) : "l"(v));
}
#define F2MUL(d,a,b)   asm("mul.rn.f32x2 %0,%1,%2;"    : "=l"(d) : "l"(a), "l"(b))
#define F2ADD(d,a,b)   asm("add.rn.f32x2 %0,%1,%2;"    : "=l"(d) : "l"(a), "l"(b))
#define F2FMA(d,a,b,c) asm("fma.rn.f32x2 %0,%1,%2,%3;" : "=l"(d) : "l"(a), "l"(b), "l"(c))

// ---------------- init: all tables (double precision) ---------------------
__global__ void init_tables() {
    int gid = blockIdx.x * blockDim.x + threadIdx.x;   // 64*256 = 16384
    if (gid < 256) {
        double a = -2.0 * PI_D * (double)gid / (double)NH;
        d_twf[gid] = make_float2((float)cos(a), (float)sin(a));
    }
    if (gid < NH) {
        double a = -2.0 * PI_D * (double)gid / (double)(2 * NH);
        d_twu[gid] = make_float2((float)cos(a), (float)sin(a));
        double om = 2.0 * PI_D * (double)gid / ((double)TT_LEN * (double)(TT_LEN - 1));
        d_cwT[gid] = (float)cos(om);
        d_swT[gid] = (float)sin(om);
    }
    if (gid < NM * NH) {
        int m = gid >> 10, k = gid & (NH - 1);
        double om = 2.0 * PI_D * (double)k / ((double)TT_LEN * (double)(TT_LEN - 1));
        double a = om * (double)(TTILE * m);
        d_rot0[gid] = make_float2((float)cos(a), (float)sin(a));
    }
}

// ---------------- transpose: x[b][t][d] -> d_xt[b][d][t] -------------------
__global__ __launch_bounds__(256) void transpose(const float* __restrict__ x) {
    __shared__ float tile[32][33];
    const int b  = blockIdx.z;
    const int t0 = blockIdx.x * 32;
    const int d0 = blockIdx.y * 32;
    const int lx = threadIdx.x;
    const int ly = threadIdx.y;
#pragma unroll
    for (int i = 0; i < 32; i += 8)
        tile[ly + i][lx] = x[((size_t)b * TT_LEN + t0 + ly + i) * DD + d0 + lx];
    __syncthreads();
#pragma unroll
    for (int i = 0; i < 32; i += 8)
        d_xt[((size_t)b * DD + d0 + ly + i) * TT_LEN + t0 + lx] = tile[lx][ly + i];
}

__device__ __forceinline__ float2 cmulf(float2 a, float2 b) {
    return make_float2(a.x * b.x - a.y * b.y, a.x * b.y + a.y * b.x);
}
__device__ __forceinline__ float2 cadd(float2 a, float2 b) { return make_float2(a.x + b.x, a.y + b.y); }
__device__ __forceinline__ float2 csub(float2 a, float2 b) { return make_float2(a.x - b.x, a.y - b.y); }

// Real-FFT bin k (1..1023) from packed complex spectrum Z (padded layout).
__device__ __forceinline__ float2 untangle(const float2* Z, int k) {
    float2 A  = Z[IDX(k)];
    float2 Bv = Z[IDX(NH - k)];
    float2 Bc = make_float2(Bv.x, -Bv.y);
    float2 E  = make_float2(0.5f * (A.x + Bc.x), 0.5f * (A.y + Bc.y));
    float2 Od = make_float2(A.x - Bc.x, A.y - Bc.y);
    float2 O  = make_float2(0.5f * Od.y, -0.5f * Od.x);
    float2 eo = cmulf(d_twu[k], O);
    return make_float2(E.x + eo.x, E.y + eo.y);
}

// One radix-4 Stockham pass. Reads X[tid + 256q], writes Y[4*(tid&~(M-1)) + (tid&(M-1)) + q*M].
template <int M>
__device__ __forceinline__ void fft_pass(const float2* __restrict__ X,
                                         float2* __restrict__ Y, int tid) {
    float2 a = X[IDX(tid)];
    float2 b = X[IDX(tid + 256)];
    float2 c = X[IDX(tid + 512)];
    float2 d = X[IDX(tid + 768)];
    float2 t0 = cadd(a, c);
    float2 t1 = csub(a, c);
    float2 t2 = cadd(b, d);
    float2 e  = csub(b, d);
    float2 t3 = make_float2(e.y, -e.x);        // -i * (b - d)
    float2 w  = d_twf[tid & ~(M - 1)];         // exp(-2pi i (j*M)/1024), j*M < 256
    float2 w2 = cmulf(w, w);
    float2 w3 = cmulf(w2, w);
    int wb = 4 * (tid & ~(M - 1)) + (tid & (M - 1));
    Y[IDX(wb)]         = cadd(t0, t2);
    Y[IDX(wb + M)]     = cmulf(w,  cadd(t1, t3));
    Y[IDX(wb + 2 * M)] = cmulf(w2, csub(t0, t2));
    Y[IDX(wb + 3 * M)] = cmulf(w3, csub(t1, t3));
}

// ---------------- analysis: Stockham FFT + hierarchical top-16 ------------
__global__ __launch_bounds__(256) void analyze() {
    __shared__ float2 bufA[PADN];
    __shared__ float2 bufB[PADN];
    __shared__ float  cand_v[128];
    __shared__ int    cand_k[128];
    __shared__ int    sel[KSEL];

    const int tid = threadIdx.x;
    const int bd  = blockIdx.x;
    const float2* row = (const float2*)(d_xt + (size_t)bd * TT_LEN);

#pragma unroll
    for (int q = 0; q < 4; q++)
        bufA[IDX(tid + 256 * q)] = row[tid + 256 * q];
    __syncthreads();

    fft_pass<1>(bufA, bufB, tid);   __syncthreads();
    fft_pass<4>(bufB, bufA, tid);   __syncthreads();
    fft_pass<16>(bufA, bufB, tid);  __syncthreads();
    fft_pass<64>(bufB, bufA, tid);  __syncthreads();
    fft_pass<256>(bufA, bufB, tid); __syncthreads();
    // full complex spectrum now in bufB (natural order)

    // per-thread mags for bins {tid, tid+256, tid+512, tid+768}
    float m[4];
#pragma unroll
    for (int q = 0; q < 4; q++) {
        int k = tid + 256 * q;
        if (k == 0) { m[q] = -1e30f; continue; }
        float2 Xk = untangle(bufB, k);
        m[q] = Xk.x * Xk.x + Xk.y * Xk.y;
    }

    const int lane = tid & 31;
    const int warp = tid >> 5;

    // phase 1: each warp finds its local top-16 (no block syncs)
    for (int r = 0; r < KSEL; r++) {
        float v = m[0]; int bin = tid;
        if (m[1] > v) { v = m[1]; bin = tid + 256; }
        if (m[2] > v) { v = m[2]; bin = tid + 512; }
        if (m[3] > v) { v = m[3]; bin = tid + 768; }
#pragma unroll
        for (int o = 16; o > 0; o >>= 1) {
            float ov = __shfl_down_sync(0xffffffffu, v, o);
            int   ob = __shfl_down_sync(0xffffffffu, bin, o);
            if (ov > v) { v = ov; bin = ob; }
        }
        bin = __shfl_sync(0xffffffffu, bin, 0);
        v   = __shfl_sync(0xffffffffu, v, 0);
        if (lane == 0) { cand_v[warp * 16 + r] = v; cand_k[warp * 16 + r] = bin; }
        if ((bin & 31) == lane) m[bin >> 8] = -1e30f;   // clear winner
    }
    __syncthreads();

    // phase 2: warp 0 merges the 128 candidates
    if (warp == 0) {
        float cv[4]; int ck[4];
#pragma unroll
        for (int q = 0; q < 4; q++) {
            cv[q] = cand_v[lane + 32 * q];
            ck[q] = cand_k[lane + 32 * q];
        }
        for (int r = 0; r < KSEL; r++) {
            float v = cv[0]; int pos = lane;
            if (cv[1] > v) { v = cv[1]; pos = lane + 32; }
            if (cv[2] > v) { v = cv[2]; pos = lane + 64; }
            if (cv[3] > v) { v = cv[3]; pos = lane + 96; }
#pragma unroll
            for (int o = 16; o > 0; o >>= 1) {
                float ov = __shfl_down_sync(0xffffffffu, v, o);
                int   op = __shfl_down_sync(0xffffffffu, pos, o);
                if (ov > v) { v = ov; pos = op; }
            }
            pos = __shfl_sync(0xffffffffu, pos, 0);
            if (lane == 0) sel[r] = cand_k[pos];
            if ((pos & 31) == lane) cv[pos >> 5] = -1e30f;
        }
    }
    __syncthreads();

    if (tid < KSEL) {
        int k = sel[tid];
        float2 Xk = untangle(bufB, k);         // Xk = amp * e^{i ph}
        int base = bd * KSEL + tid;
        d_c0[base]  = Xk.x;
        d_s0[base]  = Xk.y;
        d_kix[base] = k;
    }
}

// ---------------- synthesis: packed-f32x2 rotation recurrence -------------
__global__ __launch_bounds__(128) void synth(float* __restrict__ out) {
    __shared__ float s_cw[NH], s_sw[NH];
    for (int i = threadIdx.x; i < NH; i += 128) {
        s_cw[i] = d_cwT[i];
        s_sw[i] = d_swT[i];
    }
    __syncthreads();

    const int b  = blockIdx.z;
    const int d  = blockIdx.y * 128 + threadIdx.x;
    const int m  = blockIdx.x;
    const int base = (b * DD + d) * KSEL;
    const float2* rot = d_rot0 + m * NH;

    float cs[KSEL], ss[KSEL], cws[KSEL], sws[KSEL];
#pragma unroll
    for (int r = 0; r < KSEL; r++) {
        int    k  = d_kix[base + r];
        float  c0 = d_c0[base + r];
        float  s0 = d_s0[base + r];
        float2 rk = rot[k];
        cs[r]  = fmaf(c0, rk.x, -s0 * rk.y);
        ss[r]  = fmaf(c0, rk.y,  s0 * rk.x);
        cws[r] = s_cw[k];
        sws[r] = s_sw[k];
    }

    u64 C[8], S[8], CW[8], SW[8], NSW[8];
#pragma unroll
    for (int p = 0; p < 8; p++) {
        C[p]   = pk(cs[2 * p], cs[2 * p + 1]);
        S[p]   = pk(ss[2 * p], ss[2 * p + 1]);
        CW[p]  = pk(cws[2 * p], cws[2 * p + 1]);
        SW[p]  = pk(sws[2 * p], sws[2 * p + 1]);
        NSW[p] = pk(-sws[2 * p], -sws[2 * p + 1]);
    }

    float* po = out + ((size_t)b * TT_LEN + m * TTILE) * DD + d;
#pragma unroll 4
    for (int tt = 0; tt < TTILE; tt++) {
        u64 a0, a1, a2, a3;
        F2ADD(a0, C[0], C[1]);
        F2ADD(a1, C[2], C[3]);
        F2ADD(a2, C[4], C[5]);
        F2ADD(a3, C[6], C[7]);
        F2ADD(a0, a0, a1);
        F2ADD(a2, a2, a3);
        F2ADD(a0, a0, a2);
        float lo, hi;
        upk(a0, lo, hi);
        po[(size_t)tt * DD] = lo + hi;

#pragma unroll
        for (int p = 0; p < 8; p++) {
            u64 t1, t2, nc, ns;
            F2MUL(t1, C[p], CW[p]);
            F2FMA(nc, S[p], NSW[p], t1);
            F2MUL(t2, S[p], CW[p]);
            F2FMA(ns, C[p], SW[p], t2);
            C[p] = nc;
            S[p] = ns;
        }
    }
}

// ---------------- launch ---------------------------------------------------
extern "C" void kernel_launch(void* const* d_in, const int* in_sizes, int n_in,
                              void* d_out, int out_size) {
    const float* x = (const float*)d_in[0];
    float* out = (float*)d_out;

    init_tables<<<64, 256>>>();
    transpose<<<dim3(TT_LEN / 32, DD / 32, BB), dim3(32, 8)>>>(x);
    analyze<<<BB * DD, 256>>>();
    synth<<<dim3(NM, DD / 128, BB), 128>>>(out);
}

// round 4
// speedup vs baseline: 2.8609x; 1.3376x over previous
#include <cuda_runtime.h>
#include <math.h>
#include <stdint.h>

#define BB 32
#define TT_LEN 2048
#define DD 512
#define NH 1024        // complex FFT length (real length 2048)
#define KSEL 16
#define TTILE 128
#define NM (TT_LEN / TTILE)
#define PI_D 3.14159265358979323846

// padded smem indexing: kills store bank conflicts in Stockham passes
#define IDX(i) ((i) + ((i) >> 5))
#define PADN (NH + NH / 32)   // 1056

// ---------------- device scratch ------------------------------------------
__device__ float  d_xt[(size_t)BB * DD * TT_LEN];   // transposed input [b][d][t]
__device__ float2 d_twf[256];        // exp(-2pi i j / 1024), j<256
__device__ float2 d_twu[NH];         // untangle twiddles exp(-2pi i k / 2048)
__device__ float  d_cwT[NH];         // cos(omega_k)
__device__ float  d_swT[NH];         // sin(omega_k)
__device__ float2 d_rot0[NM * NH];   // e^{i omega_k * TTILE * m}
__device__ float  d_c0[BB * DD * KSEL];
__device__ float  d_s0[BB * DD * KSEL];
__device__ int    d_kix[BB * DD * KSEL];

// ---------------- packed f32x2 helpers ------------------------------------
typedef unsigned long long u64;
__device__ __forceinline__ u64 pk(float lo, float hi) {
    u64 r; asm("mov.b64 %0,{%1,%2};" : "=l"(r) : "f"(lo), "f"(hi)); return r;
}
__device__ __forceinline__ void upk(u64 v, float& lo, float& hi) {
    asm("mov.b64 {%0,%1},%2;" : "=f"(lo), "=f"(hi) : "l"(v));
}
#define F2MUL(d,a,b)   asm("mul.rn.f32x2 %0,%1,%2;"    : "=l"(d) : "l"(a), "l"(b))
#define F2ADD(d,a,b)   asm("add.rn.f32x2 %0,%1,%2;"    : "=l"(d) : "l"(a), "l"(b))
#define F2FMA(d,a,b,c) asm("fma.rn.f32x2 %0,%1,%2,%3;" : "=l"(d) : "l"(a), "l"(b), "l"(c))

// ---------------- init: all tables (double precision) ---------------------
__global__ void init_tables() {
    int gid = blockIdx.x * blockDim.x + threadIdx.x;   // 64*256 = 16384
    if (gid < 256) {
        double a = -2.0 * PI_D * (double)gid / (double)NH;
        d_twf[gid] = make_float2((float)cos(a), (float)sin(a));
    }
    if (gid < NH) {
        double a = -2.0 * PI_D * (double)gid / (double)(2 * NH);
        d_twu[gid] = make_float2((float)cos(a), (float)sin(a));
        double om = 2.0 * PI_D * (double)gid / ((double)TT_LEN * (double)(TT_LEN - 1));
        d_cwT[gid] = (float)cos(om);
        d_swT[gid] = (float)sin(om);
    }
    if (gid < NM * NH) {
        int m = gid >> 10, k = gid & (NH - 1);
        double om = 2.0 * PI_D * (double)k / ((double)TT_LEN * (double)(TT_LEN - 1));
        double a = om * (double)(TTILE * m);
        d_rot0[gid] = make_float2((float)cos(a), (float)sin(a));
    }
}

// ---------------- transpose: x[b][t][d] -> d_xt[b][d][t] -------------------
__global__ __launch_bounds__(256) void transpose(const float* __restrict__ x) {
    __shared__ float tile[32][33];
    const int b  = blockIdx.z;
    const int t0 = blockIdx.x * 32;
    const int d0 = blockIdx.y * 32;
    const int lx = threadIdx.x;
    const int ly = threadIdx.y;
#pragma unroll
    for (int i = 0; i < 32; i += 8)
        tile[ly + i][lx] = x[((size_t)b * TT_LEN + t0 + ly + i) * DD + d0 + lx];
    __syncthreads();
#pragma unroll
    for (int i = 0; i < 32; i += 8)
        d_xt[((size_t)b * DD + d0 + ly + i) * TT_LEN + t0 + lx] = tile[lx][ly + i];
}

__device__ __forceinline__ float2 cmulf(float2 a, float2 b) {
    return make_float2(a.x * b.x - a.y * b.y, a.x * b.y + a.y * b.x);
}
__device__ __forceinline__ float2 cadd(float2 a, float2 b) { return make_float2(a.x + b.x, a.y + b.y); }
__device__ __forceinline__ float2 csub(float2 a, float2 b) { return make_float2(a.x - b.x, a.y - b.y); }

// Real-FFT bin k (1..1023) from packed complex spectrum Z (padded layout).
__device__ __forceinline__ float2 untangle(const float2* Z, int k) {
    float2 A  = Z[IDX(k)];
    float2 Bv = Z[IDX(NH - k)];
    float2 Bc = make_float2(Bv.x, -Bv.y);
    float2 E  = make_float2(0.5f * (A.x + Bc.x), 0.5f * (A.y + Bc.y));
    float2 Od = make_float2(A.x - Bc.x, A.y - Bc.y);
    float2 O  = make_float2(0.5f * Od.y, -0.5f * Od.x);
    float2 eo = cmulf(d_twu[k], O);
    return make_float2(E.x + eo.x, E.y + eo.y);
}

// One radix-4 Stockham pass.
template <int M>
__device__ __forceinline__ void fft_pass(const float2* __restrict__ X,
                                         float2* __restrict__ Y, int tid) {
    float2 a = X[IDX(tid)];
    float2 b = X[IDX(tid + 256)];
    float2 c = X[IDX(tid + 512)];
    float2 d = X[IDX(tid + 768)];
    float2 t0 = cadd(a, c);
    float2 t1 = csub(a, c);
    float2 t2 = cadd(b, d);
    float2 e  = csub(b, d);
    float2 t3 = make_float2(e.y, -e.x);        // -i * (b - d)
    float2 w  = d_twf[tid & ~(M - 1)];
    float2 w2 = cmulf(w, w);
    float2 w3 = cmulf(w2, w);
    int wb = 4 * (tid & ~(M - 1)) + (tid & (M - 1));
    Y[IDX(wb)]         = cadd(t0, t2);
    Y[IDX(wb + M)]     = cmulf(w,  cadd(t1, t3));
    Y[IDX(wb + 2 * M)] = cmulf(w2, csub(t0, t2));
    Y[IDX(wb + 3 * M)] = cmulf(w3, csub(t1, t3));
}

// ---------------- analysis: Stockham FFT + REDUX-based top-16 -------------
__global__ __launch_bounds__(256) void analyze() {
    __shared__ float2   bufA[PADN];
    __shared__ float2   bufB[PADN];
    __shared__ unsigned cand_v[8 * KSEL];
    __shared__ int      cand_k[8 * KSEL];
    __shared__ int      sel[KSEL];

    const int tid = threadIdx.x;
    const int bd  = blockIdx.x;
    const float2* row = (const float2*)(d_xt + (size_t)bd * TT_LEN);

#pragma unroll
    for (int q = 0; q < 4; q++)
        bufA[IDX(tid + 256 * q)] = row[tid + 256 * q];
    __syncthreads();

    fft_pass<1>(bufA, bufB, tid);   __syncthreads();
    fft_pass<4>(bufB, bufA, tid);   __syncthreads();
    fft_pass<16>(bufA, bufB, tid);  __syncthreads();
    fft_pass<64>(bufB, bufA, tid);  __syncthreads();
    fft_pass<256>(bufA, bufB, tid); __syncthreads();
    // full complex spectrum in bufB (natural order)

    // mags as monotonic uint bits (mag^2 >= 0); bin 0 masked to 0
    unsigned u0, u1, u2, u3;
    int      k0 = tid, k1 = tid + 256, k2 = tid + 512, k3 = tid + 768;
    {
        float2 X1 = untangle(bufB, k1);
        float2 X2 = untangle(bufB, k2);
        float2 X3 = untangle(bufB, k3);
        u1 = __float_as_uint(X1.x * X1.x + X1.y * X1.y);
        u2 = __float_as_uint(X2.x * X2.x + X2.y * X2.y);
        u3 = __float_as_uint(X3.x * X3.x + X3.y * X3.y);
        if (tid == 0) u0 = 0u;
        else {
            float2 X0 = untangle(bufB, k0);
            u0 = __float_as_uint(X0.x * X0.x + X0.y * X0.y);
        }
    }

    // static 4-element descending sort (value, bin) in registers
#define CSWP(a, b, ka, kb) if (a < b) { unsigned tu = a; a = b; b = tu; int tk = ka; ka = kb; kb = tk; }
    CSWP(u0, u1, k0, k1)
    CSWP(u2, u3, k2, k3)
    CSWP(u0, u2, k0, k2)
    CSWP(u1, u3, k1, k3)
    CSWP(u1, u2, k1, k2)
#undef CSWP

    const int lane = tid & 31;
    const int warp = tid >> 5;
    const unsigned FULL = 0xffffffffu;

    // phase 1: per-warp top-16 via REDUX argmax over sorted heads
    for (int r = 0; r < KSEL; r++) {
        unsigned mx = __reduce_max_sync(FULL, u0);
        unsigned ball = __ballot_sync(FULL, u0 == mx);
        int wl = __ffs((int)ball) - 1;
        if (lane == wl) {
            cand_v[warp * KSEL + r] = u0;
            cand_k[warp * KSEL + r] = k0;
            u0 = u1; k0 = k1;
            u1 = u2; k1 = k2;
            u2 = u3; k2 = k3;
            u3 = 0u;
        }
    }
    __syncthreads();

    // phase 2: warp 0 merges the 8 sorted candidate lists
    if (warp == 0) {
        int ptr = 0, curk = 0;
        unsigned hv = 0u;
        if (lane < 8) { hv = cand_v[lane * KSEL]; curk = cand_k[lane * KSEL]; }
        for (int r = 0; r < KSEL; r++) {
            unsigned mx = __reduce_max_sync(FULL, hv);
            unsigned ball = __ballot_sync(FULL, hv == mx);
            int wl = __ffs((int)ball) - 1;
            int kwin = __shfl_sync(FULL, curk, wl);
            if (lane == 0) sel[r] = kwin;
            if (lane == wl) {
                ptr++;
                if (ptr < KSEL) {
                    hv = cand_v[lane * KSEL + ptr];
                    curk = cand_k[lane * KSEL + ptr];
                } else {
                    hv = 0u;
                }
            }
        }
    }
    __syncthreads();

    if (tid < KSEL) {
        int k = sel[tid];
        float2 Xk = untangle(bufB, k);         // Xk = amp * e^{i ph}
        int base = bd * KSEL + tid;
        d_c0[base]  = Xk.x;
        d_s0[base]  = Xk.y;
        d_kix[base] = k;
    }
}

// ---------------- synthesis: packed-f32x2 rotation recurrence -------------
__global__ __launch_bounds__(128) void synth(float* __restrict__ out) {
    __shared__ float s_cw[NH], s_sw[NH];
    for (int i = threadIdx.x; i < NH; i += 128) {
        s_cw[i] = d_cwT[i];
        s_sw[i] = d_swT[i];
    }
    __syncthreads();

    const int b  = blockIdx.z;
    const int d  = blockIdx.y * 128 + threadIdx.x;
    const int m  = blockIdx.x;
    const int base = (b * DD + d) * KSEL;
    const float2* rot = d_rot0 + m * NH;

    float cs[KSEL], ss[KSEL], cws[KSEL], sws[KSEL];
#pragma unroll
    for (int r = 0; r < KSEL; r++) {
        int    k  = d_kix[base + r];
        float  c0 = d_c0[base + r];
        float  s0 = d_s0[base + r];
        float2 rk = rot[k];
        cs[r]  = fmaf(c0, rk.x, -s0 * rk.y);
        ss[r]  = fmaf(c0, rk.y,  s0 * rk.x);
        cws[r] = s_cw[k];
        sws[r] = s_sw[k];
    }

    u64 C[8], S[8], CW[8], SW[8], NSW[8];
#pragma unroll
    for (int p = 0; p < 8; p++) {
        C[p]   = pk(cs[2 * p], cs[2 * p + 1]);
        S[p]   = pk(ss[2 * p], ss[2 * p + 1]);
        CW[p]  = pk(cws[2 * p], cws[2 * p + 1]);
        SW[p]  = pk(sws[2 * p], sws[2 * p + 1]);
        NSW[p] = pk(-sws[2 * p], -sws[2 * p + 1]);
    }

    float* po = out + ((size_t)b * TT_LEN + m * TTILE) * DD + d;
#pragma unroll 4
    for (int tt = 0; tt < TTILE; tt++) {
        u64 a0, a1, a2, a3;
        F2ADD(a0, C[0], C[1]);
        F2ADD(a1, C[2], C[3]);
        F2ADD(a2, C[4], C[5]);
        F2ADD(a3, C[6], C[7]);
        F2ADD(a0, a0, a1);
        F2ADD(a2, a2, a3);
        F2ADD(a0, a0, a2);
        float lo, hi;
        upk(a0, lo, hi);
        po[(size_t)tt * DD] = lo + hi;

#pragma unroll
        for (int p = 0; p < 8; p++) {
            u64 t1, t2, nc, ns;
            F2MUL(t1, C[p], CW[p]);
            F2FMA(nc, S[p], NSW[p], t1);
            F2MUL(t2, S[p], CW[p]);
            F2FMA(ns, C[p], SW[p], t2);
            C[p] = nc;
            S[p] = ns;
        }
    }
}

// ---------------- launch ---------------------------------------------------
extern "C" void kernel_launch(void* const* d_in, const int* in_sizes, int n_in,
                              void* d_out, int out_size) {
    const float* x = (const float*)d_in[0];
    float* out = (float*)d_out;

    init_tables<<<64, 256>>>();
    transpose<<<dim3(TT_LEN / 32, DD / 32, BB), dim3(32, 8)>>>(x);
    analyze<<<BB * DD, 256>>>();
    synth<<<dim3(NM, DD / 128, BB), 128>>>(out);
}

// round 5
// speedup vs baseline: 2.8837x; 1.0080x over previous
#include <cuda_runtime.h>
#include <math.h>
#include <stdint.h>

#define BB 32
#define TT_LEN 2048
#define DD 512
#define NH 1024        // complex FFT length (real length 2048)
#define KSEL 16
#define TTILE 128
#define NM (TT_LEN / TTILE)
#define PI_D 3.14159265358979323846

// padded smem indexing: kills store bank conflicts in Stockham passes
#define IDX(i) ((i) + ((i) >> 5))
#define PADN (NH + NH / 32)   // 1056

// ---------------- device scratch ------------------------------------------
__device__ float  d_xt[(size_t)BB * DD * TT_LEN];   // transposed input [b][d][t]
__device__ float2 d_twf[256];        // exp(-2pi i j / 1024), j<256
__device__ float2 d_twu[NH];         // untangle twiddles exp(-2pi i k / 2048)
__device__ float  d_nthT[NH];        // -tan(omega_k / 2)
__device__ float  d_snT[NH];         // sin(omega_k)
__device__ float2 d_rot0[NM * NH];   // e^{i omega_k * TTILE * m}
__device__ float  d_c0[BB * DD * KSEL];
__device__ float  d_s0[BB * DD * KSEL];
__device__ int    d_kix[BB * DD * KSEL];

// ---------------- packed f32x2 helpers ------------------------------------
typedef unsigned long long u64;
__device__ __forceinline__ u64 pk(float lo, float hi) {
    u64 r; asm("mov.b64 %0,{%1,%2};" : "=l"(r) : "f"(lo), "f"(hi)); return r;
}
__device__ __forceinline__ void upk(u64 v, float& lo, float& hi) {
    asm("mov.b64 {%0,%1},%2;" : "=f"(lo), "=f"(hi) : "l"(v));
}
#define F2ADD(d,a,b)   asm("add.rn.f32x2 %0,%1,%2;"    : "=l"(d) : "l"(a), "l"(b))
#define F2FMA(d,a,b,c) asm("fma.rn.f32x2 %0,%1,%2,%3;" : "=l"(d) : "l"(a), "l"(b), "l"(c))

// ---------------- init: all tables (double precision) ---------------------
__global__ void init_tables() {
    int gid = blockIdx.x * blockDim.x + threadIdx.x;   // 64*256 = 16384
    if (gid < 256) {
        double a = -2.0 * PI_D * (double)gid / (double)NH;
        d_twf[gid] = make_float2((float)cos(a), (float)sin(a));
    }
    if (gid < NH) {
        double a = -2.0 * PI_D * (double)gid / (double)(2 * NH);
        d_twu[gid] = make_float2((float)cos(a), (float)sin(a));
        double om = 2.0 * PI_D * (double)gid / ((double)TT_LEN * (double)(TT_LEN - 1));
        d_nthT[gid] = (float)(-tan(om * 0.5));
        d_snT[gid]  = (float)sin(om);
    }
    if (gid < NM * NH) {
        int m = gid >> 10, k = gid & (NH - 1);
        double om = 2.0 * PI_D * (double)k / ((double)TT_LEN * (double)(TT_LEN - 1));
        double a = om * (double)(TTILE * m);
        d_rot0[gid] = make_float2((float)cos(a), (float)sin(a));
    }
}

// ---------------- transpose: x[b][t][d] -> d_xt[b][d][t] -------------------
__global__ __launch_bounds__(256) void transpose(const float* __restrict__ x) {
    __shared__ float tile[32][33];
    const int b  = blockIdx.z;
    const int t0 = blockIdx.x * 32;
    const int d0 = blockIdx.y * 32;
    const int lx = threadIdx.x;
    const int ly = threadIdx.y;
#pragma unroll
    for (int i = 0; i < 32; i += 8)
        tile[ly + i][lx] = x[((size_t)b * TT_LEN + t0 + ly + i) * DD + d0 + lx];
    __syncthreads();
#pragma unroll
    for (int i = 0; i < 32; i += 8)
        d_xt[((size_t)b * DD + d0 + ly + i) * TT_LEN + t0 + lx] = tile[lx][ly + i];
}

__device__ __forceinline__ float2 cmulf(float2 a, float2 b) {
    return make_float2(a.x * b.x - a.y * b.y, a.x * b.y + a.y * b.x);
}
__device__ __forceinline__ float2 cadd(float2 a, float2 b) { return make_float2(a.x + b.x, a.y + b.y); }
__device__ __forceinline__ float2 csub(float2 a, float2 b) { return make_float2(a.x - b.x, a.y - b.y); }

// Real-FFT bin k (1..1023) from packed complex spectrum Z (padded layout).
__device__ __forceinline__ float2 untangle(const float2* Z, int k) {
    float2 A  = Z[IDX(k)];
    float2 Bv = Z[IDX(NH - k)];
    float2 Bc = make_float2(Bv.x, -Bv.y);
    float2 E  = make_float2(0.5f * (A.x + Bc.x), 0.5f * (A.y + Bc.y));
    float2 Od = make_float2(A.x - Bc.x, A.y - Bc.y);
    float2 O  = make_float2(0.5f * Od.y, -0.5f * Od.x);
    float2 eo = cmulf(d_twu[k], O);
    return make_float2(E.x + eo.x, E.y + eo.y);
}

// One radix-4 Stockham pass.
template <int M>
__device__ __forceinline__ void fft_pass(const float2* __restrict__ X,
                                         float2* __restrict__ Y, int tid) {
    float2 a = X[IDX(tid)];
    float2 b = X[IDX(tid + 256)];
    float2 c = X[IDX(tid + 512)];
    float2 d = X[IDX(tid + 768)];
    float2 t0 = cadd(a, c);
    float2 t1 = csub(a, c);
    float2 t2 = cadd(b, d);
    float2 e  = csub(b, d);
    float2 t3 = make_float2(e.y, -e.x);        // -i * (b - d)
    float2 w  = d_twf[tid & ~(M - 1)];
    float2 w2 = cmulf(w, w);
    float2 w3 = cmulf(w2, w);
    int wb = 4 * (tid & ~(M - 1)) + (tid & (M - 1));
    Y[IDX(wb)]         = cadd(t0, t2);
    Y[IDX(wb + M)]     = cmulf(w,  cadd(t1, t3));
    Y[IDX(wb + 2 * M)] = cmulf(w2, csub(t0, t2));
    Y[IDX(wb + 3 * M)] = cmulf(w3, csub(t1, t3));
}

// ---------------- analysis: Stockham FFT + REDUX-based top-16 -------------
__global__ __launch_bounds__(256) void analyze() {
    __shared__ float2   bufA[PADN];
    __shared__ float2   bufB[PADN];
    __shared__ unsigned cand_v[8 * KSEL];
    __shared__ int      cand_k[8 * KSEL];
    __shared__ int      sel[KSEL];

    const int tid = threadIdx.x;
    const int bd  = blockIdx.x;
    const float4* row4 = (const float4*)(d_xt + (size_t)bd * TT_LEN);

    // float4 load: 2 complex points per LDG.128
#pragma unroll
    for (int q = 0; q < 2; q++) {
        int j = tid + 256 * q;
        float4 v = row4[j];
        bufA[IDX(2 * j)]     = make_float2(v.x, v.y);
        bufA[IDX(2 * j + 1)] = make_float2(v.z, v.w);
    }
    __syncthreads();

    fft_pass<1>(bufA, bufB, tid);   __syncthreads();
    fft_pass<4>(bufB, bufA, tid);   __syncthreads();
    fft_pass<16>(bufA, bufB, tid);  __syncthreads();
    fft_pass<64>(bufB, bufA, tid);  __syncthreads();
    fft_pass<256>(bufA, bufB, tid); __syncthreads();
    // full complex spectrum in bufB (natural order)

    // mags as monotonic uint bits (mag^2 >= 0); bin 0 masked to 0
    unsigned u0, u1, u2, u3;
    int      k0 = tid, k1 = tid + 256, k2 = tid + 512, k3 = tid + 768;
    {
        float2 X1 = untangle(bufB, k1);
        float2 X2 = untangle(bufB, k2);
        float2 X3 = untangle(bufB, k3);
        u1 = __float_as_uint(X1.x * X1.x + X1.y * X1.y);
        u2 = __float_as_uint(X2.x * X2.x + X2.y * X2.y);
        u3 = __float_as_uint(X3.x * X3.x + X3.y * X3.y);
        if (tid == 0) u0 = 0u;
        else {
            float2 X0 = untangle(bufB, k0);
            u0 = __float_as_uint(X0.x * X0.x + X0.y * X0.y);
        }
    }

    // static 4-element descending sort (value, bin) in registers
#define CSWP(a, b, ka, kb) if (a < b) { unsigned tu = a; a = b; b = tu; int tk = ka; ka = kb; kb = tk; }
    CSWP(u0, u1, k0, k1)
    CSWP(u2, u3, k2, k3)
    CSWP(u0, u2, k0, k2)
    CSWP(u1, u3, k1, k3)
    CSWP(u1, u2, k1, k2)
#undef CSWP

    const int lane = tid & 31;
    const int warp = tid >> 5;
    const unsigned FULL = 0xffffffffu;

    // phase 1: per-warp top-16 via REDUX argmax over sorted heads
    for (int r = 0; r < KSEL; r++) {
        unsigned mx = __reduce_max_sync(FULL, u0);
        unsigned ball = __ballot_sync(FULL, u0 == mx);
        int wl = __ffs((int)ball) - 1;
        if (lane == wl) {
            cand_v[warp * KSEL + r] = u0;
            cand_k[warp * KSEL + r] = k0;
            u0 = u1; k0 = k1;
            u1 = u2; k1 = k2;
            u2 = u3; k2 = k3;
            u3 = 0u;
        }
    }
    __syncthreads();

    // phase 2: warp 0 merges the 8 sorted candidate lists
    if (warp == 0) {
        int ptr = 0, curk = 0;
        unsigned hv = 0u;
        if (lane < 8) { hv = cand_v[lane * KSEL]; curk = cand_k[lane * KSEL]; }
        for (int r = 0; r < KSEL; r++) {
            unsigned mx = __reduce_max_sync(FULL, hv);
            unsigned ball = __ballot_sync(FULL, hv == mx);
            int wl = __ffs((int)ball) - 1;
            int kwin = __shfl_sync(FULL, curk, wl);
            if (lane == 0) sel[r] = kwin;
            if (lane == wl) {
                ptr++;
                if (ptr < KSEL) {
                    hv = cand_v[lane * KSEL + ptr];
                    curk = cand_k[lane * KSEL + ptr];
                } else {
                    hv = 0u;
                }
            }
        }
    }
    __syncthreads();

    if (tid < KSEL) {
        int k = sel[tid];
        float2 Xk = untangle(bufB, k);         // Xk = amp * e^{i ph}
        int base = bd * KSEL + tid;
        d_c0[base]  = Xk.x;
        d_s0[base]  = Xk.y;
        d_kix[base] = k;
    }
}

// ---------------- synthesis: packed-f32x2 3-shear rotation ----------------
// R(w) = S1*S2*S1:  u = c + nth*s ; s' = s + sn*u ; c' = u + nth*s'
// with nth = -tan(w/2), sn = sin(w).  Exact rotation, 3 FMAs per pair.
__global__ __launch_bounds__(128) void synth(float* __restrict__ out) {
    __shared__ float s_nth[NH], s_sn[NH];
    for (int i = threadIdx.x; i < NH; i += 128) {
        s_nth[i] = d_nthT[i];
        s_sn[i]  = d_snT[i];
    }
    __syncthreads();

    const int b  = blockIdx.z;
    const int d  = blockIdx.y * 128 + threadIdx.x;
    const int m  = blockIdx.x;
    const int base = (b * DD + d) * KSEL;
    const float2* rot = d_rot0 + m * NH;

    float cs[KSEL], ss[KSEL], nths[KSEL], sns[KSEL];
#pragma unroll
    for (int r = 0; r < KSEL; r++) {
        int    k  = d_kix[base + r];
        float  c0 = d_c0[base + r];
        float  s0 = d_s0[base + r];
        float2 rk = rot[k];
        cs[r]   = fmaf(c0, rk.x, -s0 * rk.y);
        ss[r]   = fmaf(c0, rk.y,  s0 * rk.x);
        nths[r] = s_nth[k];
        sns[r]  = s_sn[k];
    }

    u64 C[8], S[8], NTH[8], SN[8];
#pragma unroll
    for (int p = 0; p < 8; p++) {
        C[p]   = pk(cs[2 * p], cs[2 * p + 1]);
        S[p]   = pk(ss[2 * p], ss[2 * p + 1]);
        NTH[p] = pk(nths[2 * p], nths[2 * p + 1]);
        SN[p]  = pk(sns[2 * p], sns[2 * p + 1]);
    }

    float* po = out + ((size_t)b * TT_LEN + m * TTILE) * DD + d;
#pragma unroll 4
    for (int tt = 0; tt < TTILE; tt++) {
        u64 a0, a1, a2, a3;
        F2ADD(a0, C[0], C[1]);
        F2ADD(a1, C[2], C[3]);
        F2ADD(a2, C[4], C[5]);
        F2ADD(a3, C[6], C[7]);
        F2ADD(a0, a0, a1);
        F2ADD(a2, a2, a3);
        F2ADD(a0, a0, a2);
        float lo, hi;
        upk(a0, lo, hi);
        po[(size_t)tt * DD] = lo + hi;

        // 3-shear rotation: u = C + NTH*S ; S += SN*u ; C = u + NTH*S
#pragma unroll
        for (int p = 0; p < 8; p++) {
            u64 u;
            F2FMA(u, NTH[p], S[p], C[p]);
            F2FMA(S[p], SN[p], u, S[p]);
            F2FMA(C[p], NTH[p], S[p], u);
        }
    }
}

// ---------------- launch ---------------------------------------------------
extern "C" void kernel_launch(void* const* d_in, const int* in_sizes, int n_in,
                              void* d_out, int out_size) {
    const float* x = (const float*)d_in[0];
    float* out = (float*)d_out;

    init_tables<<<64, 256>>>();
    transpose<<<dim3(TT_LEN / 32, DD / 32, BB), dim3(32, 8)>>>(x);
    analyze<<<BB * DD, 256>>>();
    synth<<<dim3(NM, DD / 128, BB), 128>>>(out);
}

// round 6
// speedup vs baseline: 2.9613x; 1.0269x over previous
#include <cuda_runtime.h>
#include <math.h>
#include <stdint.h>

#define BB 32
#define TT_LEN 2048
#define DD 512
#define NH 1024        // complex FFT length (real length 2048)
#define KSEL 16
#define TTILE 128
#define NM (TT_LEN / TTILE)
#define PI_D 3.14159265358979323846

// padded smem indexing: kills store bank conflicts in Stockham passes
#define IDX(i) ((i) + ((i) >> 5))
#define PADN (NH + NH / 32)   // 1056

// ---------------- device scratch ------------------------------------------
__device__ float  d_xt[(size_t)BB * DD * TT_LEN];   // transposed input [b][d][t]
__device__ float2 d_twf[256];        // w  = exp(-2pi i j / 1024)
__device__ float2 d_twf2[256];       // w^2
__device__ float2 d_twf3[256];       // w^3
__device__ float2 d_twu[NH];         // untangle twiddles exp(-2pi i k / 2048)
__device__ float  d_cwT[NH];         // cos(omega_k)
__device__ float  d_swT[NH];         // sin(omega_k)
__device__ float  d_eT[NH];          // -4 sin^2(omega_k/2)  (Reinsch coefficient)
__device__ float2 d_rot0[NM * NH];   // e^{i omega_k * TTILE * m}
__device__ float  d_c0[BB * DD * KSEL];
__device__ float  d_s0[BB * DD * KSEL];
__device__ int    d_kix[BB * DD * KSEL];

// ---------------- packed f32x2 helpers ------------------------------------
typedef unsigned long long u64;
__device__ __forceinline__ u64 pk(float lo, float hi) {
    u64 r; asm("mov.b64 %0,{%1,%2};" : "=l"(r) : "f"(lo), "f"(hi)); return r;
}
__device__ __forceinline__ void upk(u64 v, float& lo, float& hi) {
    asm("mov.b64 {%0,%1},%2;" : "=f"(lo), "=f"(hi) : "l"(v));
}
#define F2ADD(d,a,b)   asm("add.rn.f32x2 %0,%1,%2;"    : "=l"(d) : "l"(a), "l"(b))
#define F2FMA(d,a,b,c) asm("fma.rn.f32x2 %0,%1,%2,%3;" : "=l"(d) : "l"(a), "l"(b), "l"(c))

// ---------------- init: all tables (double precision) ---------------------
__global__ void init_tables() {
    int gid = blockIdx.x * blockDim.x + threadIdx.x;   // 64*256 = 16384
    if (gid < 256) {
        double a = -2.0 * PI_D * (double)gid / (double)NH;
        d_twf[gid]  = make_float2((float)cos(a), (float)sin(a));
        d_twf2[gid] = make_float2((float)cos(2 * a), (float)sin(2 * a));
        d_twf3[gid] = make_float2((float)cos(3 * a), (float)sin(3 * a));
    }
    if (gid < NH) {
        double a = -2.0 * PI_D * (double)gid / (double)(2 * NH);
        d_twu[gid] = make_float2((float)cos(a), (float)sin(a));
        double om = 2.0 * PI_D * (double)gid / ((double)TT_LEN * (double)(TT_LEN - 1));
        d_cwT[gid] = (float)cos(om);
        d_swT[gid] = (float)sin(om);
        double sh = sin(om * 0.5);
        d_eT[gid]  = (float)(-4.0 * sh * sh);
    }
    if (gid < NM * NH) {
        int m = gid >> 10, k = gid & (NH - 1);
        double om = 2.0 * PI_D * (double)k / ((double)TT_LEN * (double)(TT_LEN - 1));
        double a = om * (double)(TTILE * m);
        d_rot0[gid] = make_float2((float)cos(a), (float)sin(a));
    }
}

// ---------------- transpose: x[b][t][d] -> d_xt[b][d][t] -------------------
__global__ __launch_bounds__(256) void transpose(const float* __restrict__ x) {
    __shared__ float tile[32][33];
    const int b  = blockIdx.z;
    const int t0 = blockIdx.x * 32;
    const int d0 = blockIdx.y * 32;
    const int lx = threadIdx.x;
    const int ly = threadIdx.y;
#pragma unroll
    for (int i = 0; i < 32; i += 8)
        tile[ly + i][lx] = x[((size_t)b * TT_LEN + t0 + ly + i) * DD + d0 + lx];
    __syncthreads();
#pragma unroll
    for (int i = 0; i < 32; i += 8)
        d_xt[((size_t)b * DD + d0 + ly + i) * TT_LEN + t0 + lx] = tile[lx][ly + i];
}

__device__ __forceinline__ float2 cmulf(float2 a, float2 b) {
    return make_float2(a.x * b.x - a.y * b.y, a.x * b.y + a.y * b.x);
}
__device__ __forceinline__ float2 cadd(float2 a, float2 b) { return make_float2(a.x + b.x, a.y + b.y); }
__device__ __forceinline__ float2 csub(float2 a, float2 b) { return make_float2(a.x - b.x, a.y - b.y); }

// Real-FFT bin k (1..1023) from packed complex spectrum Z (padded layout).
__device__ __forceinline__ float2 untangle(const float2* Z, int k) {
    float2 A  = Z[IDX(k)];
    float2 Bv = Z[IDX(NH - k)];
    float2 Bc = make_float2(Bv.x, -Bv.y);
    float2 E  = make_float2(0.5f * (A.x + Bc.x), 0.5f * (A.y + Bc.y));
    float2 Od = make_float2(A.x - Bc.x, A.y - Bc.y);
    float2 O  = make_float2(0.5f * Od.y, -0.5f * Od.x);
    float2 eo = cmulf(d_twu[k], O);
    return make_float2(E.x + eo.x, E.y + eo.y);
}

// One radix-4 Stockham pass.  Final pass (M=256) has w=1: no twiddle mults.
template <int M>
__device__ __forceinline__ void fft_pass(const float2* __restrict__ X,
                                         float2* __restrict__ Y, int tid) {
    float2 a = X[IDX(tid)];
    float2 b = X[IDX(tid + 256)];
    float2 c = X[IDX(tid + 512)];
    float2 d = X[IDX(tid + 768)];
    float2 t0 = cadd(a, c);
    float2 t1 = csub(a, c);
    float2 t2 = cadd(b, d);
    float2 e  = csub(b, d);
    float2 t3 = make_float2(e.y, -e.x);        // -i * (b - d)
    int wb = 4 * (tid & ~(M - 1)) + (tid & (M - 1));
    if constexpr (M == 256) {
        Y[IDX(wb)]         = cadd(t0, t2);
        Y[IDX(wb + M)]     = cadd(t1, t3);
        Y[IDX(wb + 2 * M)] = csub(t0, t2);
        Y[IDX(wb + 3 * M)] = csub(t1, t3);
    } else {
        int j = tid & ~(M - 1);
        float2 w  = d_twf[j];
        float2 w2 = d_twf2[j];
        float2 w3 = d_twf3[j];
        Y[IDX(wb)]         = cadd(t0, t2);
        Y[IDX(wb + M)]     = cmulf(w,  cadd(t1, t3));
        Y[IDX(wb + 2 * M)] = cmulf(w2, csub(t0, t2));
        Y[IDX(wb + 3 * M)] = cmulf(w3, csub(t1, t3));
    }
}

// ---------------- analysis: Stockham FFT + REDUX-based top-16 -------------
__global__ __launch_bounds__(256) void analyze() {
    __shared__ float2   bufA[PADN];
    __shared__ float2   bufB[PADN];
    __shared__ unsigned cand_v[8 * KSEL];
    __shared__ int      cand_k[8 * KSEL];
    __shared__ int      sel[KSEL];

    const int tid = threadIdx.x;
    const int bd  = blockIdx.x;
    const float4* row4 = (const float4*)(d_xt + (size_t)bd * TT_LEN);

#pragma unroll
    for (int q = 0; q < 2; q++) {
        int j = tid + 256 * q;
        float4 v = row4[j];
        bufA[IDX(2 * j)]     = make_float2(v.x, v.y);
        bufA[IDX(2 * j + 1)] = make_float2(v.z, v.w);
    }
    __syncthreads();

    fft_pass<1>(bufA, bufB, tid);   __syncthreads();
    fft_pass<4>(bufB, bufA, tid);   __syncthreads();
    fft_pass<16>(bufA, bufB, tid);  __syncthreads();
    fft_pass<64>(bufB, bufA, tid);  __syncthreads();
    fft_pass<256>(bufA, bufB, tid); __syncthreads();
    // full complex spectrum in bufB (natural order)

    // mags as monotonic uint bits (mag^2 >= 0); bin 0 masked to 0
    unsigned u0, u1, u2, u3;
    int      k0 = tid, k1 = tid + 256, k2 = tid + 512, k3 = tid + 768;
    {
        float2 X1 = untangle(bufB, k1);
        float2 X2 = untangle(bufB, k2);
        float2 X3 = untangle(bufB, k3);
        u1 = __float_as_uint(X1.x * X1.x + X1.y * X1.y);
        u2 = __float_as_uint(X2.x * X2.x + X2.y * X2.y);
        u3 = __float_as_uint(X3.x * X3.x + X3.y * X3.y);
        if (tid == 0) u0 = 0u;
        else {
            float2 X0 = untangle(bufB, k0);
            u0 = __float_as_uint(X0.x * X0.x + X0.y * X0.y);
        }
    }

#define CSWP(a, b, ka, kb) if (a < b) { unsigned tu = a; a = b; b = tu; int tk = ka; ka = kb; kb = tk; }
    CSWP(u0, u1, k0, k1)
    CSWP(u2, u3, k2, k3)
    CSWP(u0, u2, k0, k2)
    CSWP(u1, u3, k1, k3)
    CSWP(u1, u2, k1, k2)
#undef CSWP

    const int lane = tid & 31;
    const int warp = tid >> 5;
    const unsigned FULL = 0xffffffffu;

    // phase 1: per-warp top-16 via REDUX argmax over sorted heads
    for (int r = 0; r < KSEL; r++) {
        unsigned mx = __reduce_max_sync(FULL, u0);
        unsigned ball = __ballot_sync(FULL, u0 == mx);
        int wl = __ffs((int)ball) - 1;
        if (lane == wl) {
            cand_v[warp * KSEL + r] = u0;
            cand_k[warp * KSEL + r] = k0;
            u0 = u1; k0 = k1;
            u1 = u2; k1 = k2;
            u2 = u3; k2 = k3;
            u3 = 0u;
        }
    }
    __syncthreads();

    // phase 2: warp 0 merges the 8 sorted candidate lists
    if (warp == 0) {
        int ptr = 0, curk = 0;
        unsigned hv = 0u;
        if (lane < 8) { hv = cand_v[lane * KSEL]; curk = cand_k[lane * KSEL]; }
        for (int r = 0; r < KSEL; r++) {
            unsigned mx = __reduce_max_sync(FULL, hv);
            unsigned ball = __ballot_sync(FULL, hv == mx);
            int wl = __ffs((int)ball) - 1;
            int kwin = __shfl_sync(FULL, curk, wl);
            if (lane == 0) sel[r] = kwin;
            if (lane == wl) {
                ptr++;
                if (ptr < KSEL) {
                    hv = cand_v[lane * KSEL + ptr];
                    curk = cand_k[lane * KSEL + ptr];
                } else {
                    hv = 0u;
                }
            }
        }
    }
    __syncthreads();

    if (tid < KSEL) {
        int k = sel[tid];
        float2 Xk = untangle(bufB, k);         // Xk = amp * e^{i ph}
        int base = bd * KSEL + tid;
        d_c0[base]  = Xk.x;
        d_s0[base]  = Xk.y;
        d_kix[base] = k;
    }
}

// ---------------- synthesis: packed-f32x2 Reinsch oscillator --------------
// d_{t+1} = d_t + e*y_t ;  y_{t+1} = y_t + d_{t+1} ;  e = -4 sin^2(w/2)
// Exactly reproduces y_t = A cos(w t + phi); e carries full RELATIVE
// precision so effective-frequency error is ~eps/2 even for tiny w.
__global__ __launch_bounds__(128, 7) void synth(float* __restrict__ out) {
    const int b  = blockIdx.z;
    const int d  = blockIdx.y * 128 + threadIdx.x;
    const int m  = blockIdx.x;
    const int base = (b * DD + d) * KSEL;
    const float2* rot = d_rot0 + m * NH;

    float ys[KSEL], dss[KSEL], es[KSEL];
#pragma unroll
    for (int r = 0; r < KSEL; r++) {
        int    k  = d_kix[base + r];
        float  c0 = d_c0[base + r];
        float  s0 = d_s0[base + r];
        float2 rk = rot[k];
        float  y  = fmaf(c0, rk.x, -s0 * rk.y);      // A cos(theta0)
        float  sn = fmaf(c0, rk.y,  s0 * rk.x);      // A sin(theta0)
        float  cw = d_cwT[k];
        float  sw = d_swT[k];
        float  yp = fmaf(y, cw, sn * sw);            // A cos(theta0 - w)
        ys[r]  = y;
        dss[r] = y - yp;
        es[r]  = d_eT[k];
    }

    u64 Y[8], D[8], E[8];
#pragma unroll
    for (int p = 0; p < 8; p++) {
        Y[p] = pk(ys[2 * p],  ys[2 * p + 1]);
        D[p] = pk(dss[2 * p], dss[2 * p + 1]);
        E[p] = pk(es[2 * p],  es[2 * p + 1]);
    }

    float* po = out + ((size_t)b * TT_LEN + m * TTILE) * DD + d;
#pragma unroll 4
    for (int tt = 0; tt < TTILE; tt++) {
        u64 a0, a1, a2, a3;
        F2ADD(a0, Y[0], Y[1]);
        F2ADD(a1, Y[2], Y[3]);
        F2ADD(a2, Y[4], Y[5]);
        F2ADD(a3, Y[6], Y[7]);
        F2ADD(a0, a0, a1);
        F2ADD(a2, a2, a3);
        F2ADD(a0, a0, a2);
        float lo, hi;
        upk(a0, lo, hi);
        po[(size_t)tt * DD] = lo + hi;

        // Reinsch advance: D += E*Y ; Y += D
#pragma unroll
        for (int p = 0; p < 8; p++) {
            F2FMA(D[p], E[p], Y[p], D[p]);
            F2ADD(Y[p], Y[p], D[p]);
        }
    }
}

// ---------------- launch ---------------------------------------------------
extern "C" void kernel_launch(void* const* d_in, const int* in_sizes, int n_in,
                              void* d_out, int out_size) {
    const float* x = (const float*)d_in[0];
    float* out = (float*)d_out;

    init_tables<<<64, 256>>>();
    transpose<<<dim3(TT_LEN / 32, DD / 32, BB), dim3(32, 8)>>>(x);
    analyze<<<BB * DD, 256>>>();
    synth<<<dim3(NM, DD / 128, BB), 128>>>(out);
}